// round 12
// baseline (speedup 1.0000x reference)
#include <cuda_runtime.h>
#include <cstdint>

// Problem dims (fixed by the dataset)
#define BATCH 16384
#define DIN   1024
#define HID   2048
#define OUTD  2

#define I8_P1 0x01u   // +1 as int8
#define I8_M1 0xFFu   // -1 as int8

// ---------------- scratch (no allocs allowed) ----------------
__device__ __align__(16) uint8_t g_act0[(size_t)BATCH * DIN];   // int8 +-1 input acts
__device__ __align__(16) uint8_t g_act1[(size_t)BATCH * HID];   // ping
__device__ __align__(16) uint8_t g_act2[(size_t)BATCH * HID];   // pong
__device__ __align__(16) uint8_t g_w1f[(size_t)HID * DIN];
__device__ __align__(16) uint8_t g_w2f[(size_t)HID * HID];
__device__ __align__(16) uint8_t g_w3f[(size_t)HID * HID];
__device__ __align__(16) uint8_t g_wof[(size_t)OUTD * HID];
__device__ float g_t1[HID], g_t2[HID], g_t3[HID];

// ================= PTX helpers (sm_80-portable only) =================
__device__ __forceinline__ uint32_t smem_u32(const void* p) {
    uint32_t a;
    asm("{ .reg .u64 t; cvta.to.shared.u64 t, %1; cvt.u32.u64 %0, t; }" : "=r"(a) : "l"(p));
    return a;
}
__device__ __forceinline__ void cp_async16(uint32_t smem, const void* gmem) {
    asm volatile("cp.async.cg.shared.global [%0], [%1], 16;" :: "r"(smem), "l"(gmem) : "memory");
}
__device__ __forceinline__ void cp_commit() { asm volatile("cp.async.commit_group;" ::: "memory"); }
template <int N>
__device__ __forceinline__ void cp_wait() { asm volatile("cp.async.wait_group %0;" :: "n"(N) : "memory"); }

__device__ __forceinline__ void ldm_x4(uint32_t& r0, uint32_t& r1, uint32_t& r2, uint32_t& r3,
                                       uint32_t addr) {
    asm volatile("ldmatrix.sync.aligned.m8n8.x4.shared.b16 {%0,%1,%2,%3}, [%4];"
                 : "=r"(r0), "=r"(r1), "=r"(r2), "=r"(r3) : "r"(addr));
}
__device__ __forceinline__ void mma_s8(int& c0, int& c1, int& c2, int& c3,
                                       uint32_t a0, uint32_t a1, uint32_t a2, uint32_t a3,
                                       uint32_t b0, uint32_t b1) {
    asm volatile(
        "mma.sync.aligned.m16n8k32.row.col.s32.s8.s8.s32 "
        "{%0,%1,%2,%3}, {%4,%5,%6,%7}, {%8,%9}, {%0,%1,%2,%3};"
        : "+r"(c0), "+r"(c1), "+r"(c2), "+r"(c3)
        : "r"(a0), "r"(a1), "r"(a2), "r"(a3), "r"(b0), "r"(b1));
}

// ---------------- packs / thresholds ----------------
__global__ void pack_i8_kernel(const float4* __restrict__ src, uint32_t* __restrict__ dst,
                               int nwords, float thresh) {
    int i = blockIdx.x * blockDim.x + threadIdx.x;
    if (i >= nwords) return;
    float4 v = src[i];
    uint32_t b0 = (v.x >= thresh) ? I8_P1 : I8_M1;
    uint32_t b1 = (v.y >= thresh) ? I8_P1 : I8_M1;
    uint32_t b2 = (v.z >= thresh) ? I8_P1 : I8_M1;
    uint32_t b3 = (v.w >= thresh) ? I8_P1 : I8_M1;
    dst[i] = b0 | (b1 << 8) | (b2 << 16) | (b3 << 24);
}

// bn(dot) >= 0  <=>  dot >= m - b/inv, inv = g*rsqrt(v+eps) > 0
__global__ void thresh_kernel(const float* __restrict__ g, const float* __restrict__ b,
                              const float* __restrict__ m, const float* __restrict__ v,
                              float* __restrict__ t, int n) {
    int j = blockIdx.x * blockDim.x + threadIdx.x;
    if (j < n) {
        float inv = g[j] * rsqrtf(v[j] + 1e-5f);
        t[j] = m[j] - b[j] / inv;
    }
}

// ---------------- int8 tensor-core layer ----------------
// CTA tile 128x128, 8 warps as 2(M)x4(N) -> warp tile 64x32.
// K staged in 64-byte chunks, double-buffered cp.async, rows padded to 80B
// (conflict-free ldmatrix: banks (20*r)%32 distinct per 8-row phase).
// Epilogue: s32 dot -> BN threshold -> int8 +-1, written directly.
#define KSTG   64
#define ROWPAD 80
#define STGSZ  (128 * ROWPAD)   // 10240 B per operand stage

template <int KTOT>
__global__ void __launch_bounds__(256, 2) binmlp_imma(
    const uint8_t* __restrict__ actin,   // [BATCH, KTOT] int8 +-1
    const uint8_t* __restrict__ wf8,     // [HID, KTOT] int8 +-1
    const float* __restrict__ th,        // [HID]
    uint8_t* __restrict__ actout) {      // [BATCH, HID] int8 +-1
    __shared__ uint8_t sm[4 * STGSZ];    // A0 A1 B0 B1

    const int tid = threadIdx.x, wid = tid >> 5, lane = tid & 31;
    const int mbase = blockIdx.x * 128;
    const int nbase = blockIdx.y * 128;
    const int mw = (wid & 1) * 64;       // warp M offset in tile
    const int nw = (wid >> 1) * 32;      // warp N offset in tile
    const uint32_t sb = smem_u32(sm);

    const int NC = KTOT / KSTG;

    // stage loader: 1024 x 16B units (A: 512, B: 512), 4 per thread
    auto load_stage = [&](int c, int s) {
        const uint8_t* Ag = actin + (size_t)mbase * KTOT + (size_t)c * KSTG;
        const uint8_t* Bg = wf8 + (size_t)nbase * KTOT + (size_t)c * KSTG;
        const uint32_t sA = sb + s * STGSZ;
        const uint32_t sB = sb + (2 + s) * STGSZ;
#pragma unroll
        for (int i = 0; i < 4; i++) {
            int u = tid + i * 256;
            int row = (u & 511) >> 2, seg = u & 3;
            if (u < 512)
                cp_async16(sA + row * ROWPAD + seg * 16, Ag + (size_t)row * KTOT + seg * 16);
            else
                cp_async16(sB + row * ROWPAD + seg * 16, Bg + (size_t)row * KTOT + seg * 16);
        }
        cp_commit();
    };

    int acc[4][4][4];
#pragma unroll
    for (int i = 0; i < 4; i++)
#pragma unroll
        for (int j = 0; j < 4; j++)
#pragma unroll
            for (int q = 0; q < 4; q++) acc[i][j][q] = 0;

    // per-lane ldmatrix base addresses (row part), col advances by 32*kk
    const int lrow = lane & 15;
    const int lcol = (lane >> 4) * 16;
    uint32_t aaddr[4], baddr[2];
#pragma unroll
    for (int i = 0; i < 4; i++) aaddr[i] = (mw + 16 * i + lrow) * ROWPAD + lcol;
#pragma unroll
    for (int j = 0; j < 2; j++) baddr[j] = (nw + 16 * j + lrow) * ROWPAD + lcol;

    load_stage(0, 0);
    if (NC > 1) load_stage(1, 1);

#pragma unroll 1
    for (int c = 0; c < NC; c++) {
        const int s = c & 1;
        if (c + 1 < NC) cp_wait<1>(); else cp_wait<0>();
        __syncthreads();

        const uint32_t sA = sb + s * STGSZ;
        const uint32_t sB = sb + (2 + s) * STGSZ;
#pragma unroll
        for (int kk = 0; kk < 2; kk++) {
            uint32_t a[4][4], b[2][4];
#pragma unroll
            for (int i = 0; i < 4; i++)
                ldm_x4(a[i][0], a[i][1], a[i][2], a[i][3], sA + aaddr[i] + 32 * kk);
#pragma unroll
            for (int j = 0; j < 2; j++)
                ldm_x4(b[j][0], b[j][1], b[j][2], b[j][3], sB + baddr[j] + 32 * kk);
#pragma unroll
            for (int i = 0; i < 4; i++) {
#pragma unroll
                for (int j = 0; j < 2; j++) {
                    mma_s8(acc[i][2 * j][0], acc[i][2 * j][1], acc[i][2 * j][2], acc[i][2 * j][3],
                           a[i][0], a[i][1], a[i][2], a[i][3], b[j][0], b[j][2]);
                    mma_s8(acc[i][2 * j + 1][0], acc[i][2 * j + 1][1], acc[i][2 * j + 1][2], acc[i][2 * j + 1][3],
                           a[i][0], a[i][1], a[i][2], a[i][3], b[j][1], b[j][3]);
                }
            }
        }
        __syncthreads();
        if (c + 2 < NC) load_stage(c + 2, s);
    }

    // Epilogue: threshold + binarize. Lane holds C[g][2t..2t+1], C[g+8][2t..2t+1].
    const int g = lane >> 2, t4 = lane & 3;
#pragma unroll
    for (int j = 0; j < 4; j++) {
        const int col = nbase + nw + 8 * j + 2 * t4;
        const float2 tv = __ldg((const float2*)&th[col]);
#pragma unroll
        for (int i = 0; i < 4; i++) {
            const int m0 = mbase + mw + 16 * i + g;
            uint32_t lo = ((float)acc[i][j][0] >= tv.x ? I8_P1 : I8_M1) |
                          (((float)acc[i][j][1] >= tv.y ? I8_P1 : I8_M1) << 8);
            uint32_t hi = ((float)acc[i][j][2] >= tv.x ? I8_P1 : I8_M1) |
                          (((float)acc[i][j][3] >= tv.y ? I8_P1 : I8_M1) << 8);
            *(uint16_t*)(actout + (size_t)m0 * HID + col) = (uint16_t)lo;
            *(uint16_t*)(actout + (size_t)(m0 + 8) * HID + col) = (uint16_t)hi;
        }
    }
}

// ---------------- final 2-neuron linear (sign-bit XOR/POPC on int8 bytes) ----------------
__global__ void outlayer_i8(const uint8_t* __restrict__ acts,
                            const uint8_t* __restrict__ wo,
                            float* __restrict__ out) {
    int gw = (blockIdx.x * blockDim.x + threadIdx.x) >> 5;
    int lane = threadIdx.x & 31;
    if (gw >= BATCH) return;
    const uint4* arow = (const uint4*)(acts + (size_t)gw * HID);
    const uint4* w0r = (const uint4*)(wo);
    const uint4* w1r = (const uint4*)(wo + HID);
    int d0 = 0, d1 = 0;
#pragma unroll
    for (int j = 0; j < 4; j++) {
        uint4 a = arow[lane + 32 * j];
        uint4 b0 = w0r[lane + 32 * j];
        uint4 b1 = w1r[lane + 32 * j];
        d0 += __popc((a.x ^ b0.x) & 0x80808080u) + __popc((a.y ^ b0.y) & 0x80808080u) +
              __popc((a.z ^ b0.z) & 0x80808080u) + __popc((a.w ^ b0.w) & 0x80808080u);
        d1 += __popc((a.x ^ b1.x) & 0x80808080u) + __popc((a.y ^ b1.y) & 0x80808080u) +
              __popc((a.z ^ b1.z) & 0x80808080u) + __popc((a.w ^ b1.w) & 0x80808080u);
    }
#pragma unroll
    for (int o = 16; o > 0; o >>= 1) {
        d0 += __shfl_xor_sync(0xffffffffu, d0, o);
        d1 += __shfl_xor_sync(0xffffffffu, d1, o);
    }
    if (lane == 0) {
        out[(size_t)gw * OUTD + 0] = (float)(HID - 2 * d0);
        out[(size_t)gw * OUTD + 1] = (float)(HID - 2 * d1);
    }
}

// ---------------- launch -------------------------------------
extern "C" void kernel_launch(void* const* d_in, const int* in_sizes, int n_in,
                              void* d_out, int out_size) {
    const float* x    = (const float*)d_in[0];
    const float* w1   = (const float*)d_in[1];
    const float* g1   = (const float*)d_in[2];
    const float* b1   = (const float*)d_in[3];
    const float* m1   = (const float*)d_in[4];
    const float* v1   = (const float*)d_in[5];
    const float* w2   = (const float*)d_in[6];
    const float* g2   = (const float*)d_in[7];
    const float* b2   = (const float*)d_in[8];
    const float* m2   = (const float*)d_in[9];
    const float* v2   = (const float*)d_in[10];
    const float* w3   = (const float*)d_in[11];
    const float* g3   = (const float*)d_in[12];
    const float* b3   = (const float*)d_in[13];
    const float* m3   = (const float*)d_in[14];
    const float* v3   = (const float*)d_in[15];
    const float* wout = (const float*)d_in[16];
    float* out = (float*)d_out;

    uint8_t *pA0, *pA1, *pA2, *pW1, *pW2, *pW3, *pWo;
    float *pt1, *pt2, *pt3;
    cudaGetSymbolAddress((void**)&pA0, g_act0);
    cudaGetSymbolAddress((void**)&pA1, g_act1);
    cudaGetSymbolAddress((void**)&pA2, g_act2);
    cudaGetSymbolAddress((void**)&pW1, g_w1f);
    cudaGetSymbolAddress((void**)&pW2, g_w2f);
    cudaGetSymbolAddress((void**)&pW3, g_w3f);
    cudaGetSymbolAddress((void**)&pWo, g_wof);
    cudaGetSymbolAddress((void**)&pt1, g_t1);
    cudaGetSymbolAddress((void**)&pt2, g_t2);
    cudaGetSymbolAddress((void**)&pt3, g_t3);

    // 1) binarize+pack input: 2x-1 >= 0 <=> x >= 0.5
    pack_i8_kernel<<<(BATCH * DIN / 4 + 255) / 256, 256>>>((const float4*)x, (uint32_t*)pA0, BATCH * DIN / 4, 0.5f);
    // 2) weights to int8 sign
    pack_i8_kernel<<<(HID * DIN / 4 + 255) / 256, 256>>>((const float4*)w1, (uint32_t*)pW1, HID * DIN / 4, 0.0f);
    pack_i8_kernel<<<(HID * HID / 4 + 255) / 256, 256>>>((const float4*)w2, (uint32_t*)pW2, HID * HID / 4, 0.0f);
    pack_i8_kernel<<<(HID * HID / 4 + 255) / 256, 256>>>((const float4*)w3, (uint32_t*)pW3, HID * HID / 4, 0.0f);
    pack_i8_kernel<<<(OUTD * HID / 4 + 255) / 256, 256>>>((const float4*)wout, (uint32_t*)pWo, OUTD * HID / 4, 0.0f);
    // 3) BN thresholds
    thresh_kernel<<<HID / 256, 256>>>(g1, b1, m1, v1, pt1, HID);
    thresh_kernel<<<HID / 256, 256>>>(g2, b2, m2, v2, pt2, HID);
    thresh_kernel<<<HID / 256, 256>>>(g3, b3, m3, v3, pt3, HID);

    // 4) three IMMA layers with fused threshold-binarize epilogue
    dim3 grid(BATCH / 128, HID / 128);
    binmlp_imma<1024><<<grid, 256>>>(pA0, pW1, pt1, pA1);
    binmlp_imma<2048><<<grid, 256>>>(pA1, pW2, pt2, pA2);
    binmlp_imma<2048><<<grid, 256>>>(pA2, pW3, pt3, pA1);

    // 5) final 2-neuron linear -> float out
    outlayer_i8<<<(BATCH * 32 + 255) / 256, 256>>>(pA1, pWo, out);
}

// round 15
// speedup vs baseline: 2.5577x; 2.5577x over previous
#include <cuda_runtime.h>
#include <cstdint>

// Problem dims (fixed by the dataset)
#define BATCH 16384
#define DIN   1024
#define HID   2048
#define OUTD  2

// ---------------- scratch (no allocs allowed) ----------------
__device__ __align__(16) uint32_t g_Wb1[HID * 32];   // w1 bits: 2048 x (1024/32)
__device__ __align__(16) uint32_t g_Wb2[HID * 64];   // w2 bits: 2048 x (2048/32)
__device__ __align__(16) uint32_t g_Wb3[HID * 64];   // w3 bits
__device__ __align__(16) uint32_t g_Wbo[OUTD * 64];  // wout bits
__device__ float g_t1[HID], g_t2[HID], g_t3[HID];    // BN thresholds
__device__ __align__(16) uint32_t g_A[BATCH * 64];   // activation bits, buffer A
__device__ __align__(16) uint32_t g_B[BATCH * 64];   // activation bits, buffer B

// ---------------- LOP3 helpers (full-adder in 2 ops) ----------------
__device__ __forceinline__ uint32_t xor3(uint32_t a, uint32_t b, uint32_t c) {
    uint32_t r;
    asm("lop3.b32 %0, %1, %2, %3, 0x96;" : "=r"(r) : "r"(a), "r"(b), "r"(c));
    return r;
}
__device__ __forceinline__ uint32_t maj3(uint32_t a, uint32_t b, uint32_t c) {
    uint32_t r;
    asm("lop3.b32 %0, %1, %2, %3, 0xE8;" : "=r"(r) : "r"(a), "r"(b), "r"(c));
    return r;
}

// ---------------- pack floats -> sign bits -------------------
// bit = (src[i] >= thresh). Launched with exactly nbits threads (multiple of 32).
__global__ void pack_bits_kernel(const float* __restrict__ src,
                                 uint32_t* __restrict__ dst,
                                 int nbits, float thresh) {
    int i = blockIdx.x * blockDim.x + threadIdx.x;
    unsigned bit = 0u;
    if (i < nbits) bit = (src[i] >= thresh) ? 1u : 0u;
    unsigned m = __ballot_sync(0xffffffffu, bit);
    if ((threadIdx.x & 31) == 0 && i < nbits) dst[i >> 5] = m;
}

// ---------------- BN -> scalar threshold ---------------------
// bn(dot) >= 0  <=>  dot >= m - b/inv, inv = g*rsqrt(v+eps) > 0
__global__ void thresh_kernel(const float* __restrict__ g,
                              const float* __restrict__ b,
                              const float* __restrict__ m,
                              const float* __restrict__ v,
                              float* __restrict__ t, int n) {
    int j = blockIdx.x * blockDim.x + threadIdx.x;
    if (j < n) {
        float inv = g[j] * rsqrtf(v[j] + 1e-5f);
        t[j] = m[j] - b[j] / inv;
    }
}

// ---------------- bit-GEMM layer (carry-save popcount) -------
// Block: 256 threads = 8 warps. Each lane owns one row (256 rows/block),
// row bits live in registers. Block covers 256 neurons (blockIdx.y), staged
// through smem in 2 chunks of 128 neurons.
// Inner loop uses two independent carry-save chains: per 2 xor-words only
// ONE popc (of the carry) is issued; Σpopc(t_i) = 2Σpopc(carry)+popc(ones).
// This moves the bottleneck off the quarter-rate POPC pipe onto full-rate LOP3.
template <int KW>  // words per input row: 32 (K=1024) or 64 (K=2048)
__global__ void __launch_bounds__(256) binlayer_kernel(
    const uint32_t* __restrict__ Xb, int xstride,
    const uint32_t* __restrict__ Wb,
    const float* __restrict__ th,
    uint32_t* __restrict__ Yb, int ystride) {
    __shared__ uint4 sW4[128 * KW / 4];
    __shared__ float sT[128];

    const int lane = threadIdx.x & 31;
    const int warp = threadIdx.x >> 5;
    const int row = blockIdx.x * 256 + warp * 32 + lane;
    const int nbase = blockIdx.y * 256;

    // Load this lane's row bits into registers.
    uint32_t x[KW];
    const uint4* xr = reinterpret_cast<const uint4*>(Xb + (size_t)row * xstride);
#pragma unroll
    for (int k = 0; k < KW / 4; k++) {
        uint4 t = xr[k];
        x[4 * k + 0] = t.x; x[4 * k + 1] = t.y;
        x[4 * k + 2] = t.z; x[4 * k + 3] = t.w;
    }

    uint32_t ow = 0;
#pragma unroll 1
    for (int c = 0; c < 2; c++) {
        __syncthreads();
        // Cooperative stage of 128 neurons' weight bits into smem.
        const uint4* wsrc =
            reinterpret_cast<const uint4*>(Wb + (size_t)(nbase + c * 128) * KW);
#pragma unroll
        for (int idx = threadIdx.x; idx < 128 * KW / 4; idx += 256)
            sW4[idx] = wsrc[idx];
        if (threadIdx.x < 128) sT[threadIdx.x] = th[nbase + c * 128 + threadIdx.x];
        __syncthreads();

#pragma unroll 1
        for (int j = 0; j < 128; j++) {
            const uint4* wp = &sW4[j * (KW / 4)];
            // Two independent carry-save chains (A: words 4k,4k+1; B: 4k+2,4k+3)
            uint32_t onesA = 0, onesB = 0;
            int acc2a = 0, acc2b = 0;
#pragma unroll
            for (int k = 0; k < KW / 4; k++) {
                uint4 w = wp[k];  // broadcast LDS.128
                uint32_t a0 = x[4 * k + 0] ^ w.x;
                uint32_t a1 = x[4 * k + 1] ^ w.y;
                uint32_t cA = maj3(onesA, a0, a1);
                onesA = xor3(onesA, a0, a1);
                uint32_t a2 = x[4 * k + 2] ^ w.z;
                uint32_t a3 = x[4 * k + 3] ^ w.w;
                uint32_t cB = maj3(onesB, a2, a3);
                onesB = xor3(onesB, a2, a3);
                acc2a += __popc(cA);
                acc2b += __popc(cB);
            }
            int total = 2 * (acc2a + acc2b) + __popc(onesA) + __popc(onesB);
            float dot = (float)(KW * 32 - 2 * total);
            unsigned bit = (dot >= sT[j]) ? 1u : 0u;
            ow |= bit << (j & 31);
            if ((j & 31) == 31) {
                int wordi = (nbase + c * 128 + j) >> 5;
                Yb[(size_t)row * ystride + wordi] = ow;
                ow = 0;
            }
        }
    }
}

// ---------------- final 2-neuron linear ----------------------
__global__ void outlayer_kernel(const uint32_t* __restrict__ Xb,
                                const uint32_t* __restrict__ Wo,
                                float* __restrict__ out) {
    int row = blockIdx.x * blockDim.x + threadIdx.x;
    if (row >= BATCH) return;
    uint32_t x[64];
    const uint4* xr = reinterpret_cast<const uint4*>(Xb + (size_t)row * 64);
#pragma unroll
    for (int k = 0; k < 16; k++) {
        uint4 t = xr[k];
        x[4 * k + 0] = t.x; x[4 * k + 1] = t.y;
        x[4 * k + 2] = t.z; x[4 * k + 3] = t.w;
    }
#pragma unroll
    for (int o = 0; o < OUTD; o++) {
        int acc = 0;
#pragma unroll
        for (int k = 0; k < 64; k++) acc += __popc(x[k] ^ Wo[o * 64 + k]);
        out[row * OUTD + o] = (float)(HID - 2 * acc);
    }
}

// ---------------- launch -------------------------------------
extern "C" void kernel_launch(void* const* d_in, const int* in_sizes, int n_in,
                              void* d_out, int out_size) {
    const float* x    = (const float*)d_in[0];
    const float* w1   = (const float*)d_in[1];
    const float* g1   = (const float*)d_in[2];
    const float* b1   = (const float*)d_in[3];
    const float* m1   = (const float*)d_in[4];
    const float* v1   = (const float*)d_in[5];
    const float* w2   = (const float*)d_in[6];
    const float* g2   = (const float*)d_in[7];
    const float* b2   = (const float*)d_in[8];
    const float* m2   = (const float*)d_in[9];
    const float* v2   = (const float*)d_in[10];
    const float* w3   = (const float*)d_in[11];
    const float* g3   = (const float*)d_in[12];
    const float* b3   = (const float*)d_in[13];
    const float* m3   = (const float*)d_in[14];
    const float* v3   = (const float*)d_in[15];
    const float* wout = (const float*)d_in[16];
    float* out = (float*)d_out;

    uint32_t *pWb1, *pWb2, *pWb3, *pWbo, *pA, *pB;
    float *pt1, *pt2, *pt3;
    cudaGetSymbolAddress((void**)&pWb1, g_Wb1);
    cudaGetSymbolAddress((void**)&pWb2, g_Wb2);
    cudaGetSymbolAddress((void**)&pWb3, g_Wb3);
    cudaGetSymbolAddress((void**)&pWbo, g_Wbo);
    cudaGetSymbolAddress((void**)&pA, g_A);
    cudaGetSymbolAddress((void**)&pB, g_B);
    cudaGetSymbolAddress((void**)&pt1, g_t1);
    cudaGetSymbolAddress((void**)&pt2, g_t2);
    cudaGetSymbolAddress((void**)&pt3, g_t3);

    // 1) binarize+pack input: 2x-1 >= 0 <=> x >= 0.5
    pack_bits_kernel<<<(BATCH * DIN) / 256, 256>>>(x, pA, BATCH * DIN, 0.5f);
    // 2) pack weights (sign bit: w >= 0)
    pack_bits_kernel<<<(HID * DIN) / 256, 256>>>(w1, pWb1, HID * DIN, 0.0f);
    pack_bits_kernel<<<(HID * HID) / 256, 256>>>(w2, pWb2, HID * HID, 0.0f);
    pack_bits_kernel<<<(HID * HID) / 256, 256>>>(w3, pWb3, HID * HID, 0.0f);
    pack_bits_kernel<<<(OUTD * HID) / 256, 256>>>(wout, pWbo, OUTD * HID, 0.0f);
    // 3) BN thresholds
    thresh_kernel<<<HID / 256, 256>>>(g1, b1, m1, v1, pt1, HID);
    thresh_kernel<<<HID / 256, 256>>>(g2, b2, m2, v2, pt2, HID);
    thresh_kernel<<<HID / 256, 256>>>(g3, b3, m3, v3, pt3, HID);

    // 4) three bit-GEMM layers (carry-save popcount)
    dim3 grid(BATCH / 256, HID / 256);
    binlayer_kernel<32><<<grid, 256>>>(pA, 32, pWb1, pt1, pB, 64);
    binlayer_kernel<64><<<grid, 256>>>(pB, 64, pWb2, pt2, pA, 64);
    binlayer_kernel<64><<<grid, 256>>>(pA, 64, pWb3, pt3, pB, 64);

    // 5) final 2-neuron linear -> float out
    outlayer_kernel<<<BATCH / 256, 256>>>(pB, pWbo, out);
}